// round 8
// baseline (speedup 1.0000x reference)
#include <cuda_runtime.h>

// Fused maxpool-argmax + sigma row-gather. (Resubmit of R6 design: prior bench
// died with cudaErrorSystemNotReady before any kernel ran — infra, not kernel.)
//
// Strategy: the scattered gather already touches every 32B sector of each
// selected row, so reading rows FULLY (coalesced float4 streaming) costs the
// same DRAM traffic. Stage 8 full rows in smem per phase, gather columns via
// LDS, write coalesced. Next phase's LDG.128s issue before the current
// gather (register double-buffer) so loads stay in flight across barriers.
//
// Grid: 128 bc * 8 chunks = 1024 blocks, 256 threads.
// Chunk owns output rows [32*chunk, 32*chunk+32); thread j owns column j.
__global__ __launch_bounds__(256, 4)
void fused_pool_gather_kernel(const float* __restrict__ mu,
                              const float* __restrict__ sigma,
                              float* __restrict__ out_mu,
                              float* __restrict__ out_sig) {
    __shared__ int   scol[256];
    __shared__ float srow[8 * 1024];      // 8 staged rows, 32 KB

    const int bc    = blockIdx.x >> 3;
    const int chunk = blockIdx.x & 7;
    const int j     = threadIdx.x;        // 0..255

    // ---- pool/argmax for window j (mu: 4KB/bc, L2-resident after first touch) ----
    const int ho = j >> 4;
    const int wo = j & 15;
    const float* base = mu + (size_t)bc * 1024;
    const int r0 = 2 * ho;
    const int c0 = 2 * wo;

    const float v0 = base[r0 * 32 + c0];
    const float v1 = base[r0 * 32 + c0 + 1];
    const float v2 = base[(r0 + 1) * 32 + c0];
    const float v3 = base[(r0 + 1) * 32 + c0 + 1];

    float m = v0; int k = 0;
    if (v1 > m) { m = v1; k = 1; }        // strict >: first-max, matches jnp.argmax
    if (v2 > m) { m = v2; k = 2; }
    if (v3 > m) { m = v3; k = 3; }

    const int cj = (r0 + (k >> 1)) * 32 + (c0 + (k & 1));
    scol[j] = cj;
    if (chunk == 0) out_mu[bc * 256 + j] = m;
    __syncthreads();

    // ---- staged row gather ----
    const float4* s4    = (const float4*)sigma + ((size_t)bc << 18);  // bc*1024*256 float4
    float*        obase = out_sig + (size_t)bc * 65536;
    const int     i0    = chunk * 32;

    // Prefetch stage 0: 8 full rows, thread j takes float4 column j of each.
    float4 v[8];
    #pragma unroll
    for (int u = 0; u < 8; ++u)
        v[u] = __ldcs(&s4[(size_t)scol[i0 + u] * 256 + j]);

    #pragma unroll
    for (int s = 0; s < 4; ++s) {
        // Commit current stage to smem.
        #pragma unroll
        for (int u = 0; u < 8; ++u) {
            float4* dst = (float4*)&srow[u * 1024] + j;
            *dst = v[u];
        }
        // Issue next stage's loads NOW — in flight during barrier + gather.
        if (s < 3) {
            #pragma unroll
            for (int u = 0; u < 8; ++u)
                v[u] = __ldcs(&s4[(size_t)scol[i0 + (s + 1) * 8 + u] * 256 + j]);
        }
        __syncthreads();

        // Gather: out[i][j] = row_i[cj]. Bank = image-col of pick; <=2-way conflicts.
        #pragma unroll
        for (int u = 0; u < 8; ++u)
            obase[(size_t)(i0 + s * 8 + u) * 256 + j] = srow[u * 1024 + cj];
        __syncthreads();                  // buffer safe to overwrite next stage
    }
}

extern "C" void kernel_launch(void* const* d_in, const int* in_sizes, int n_in,
                              void* d_out, int out_size) {
    const float* mu    = (const float*)d_in[0];
    const float* sigma = (const float*)d_in[1];
    if (n_in >= 2 && in_sizes[0] > in_sizes[1]) {
        sigma = (const float*)d_in[0];
        mu    = (const float*)d_in[1];
    }

    float* out_mu  = (float*)d_out;            // 32768 elements
    float* out_sig = out_mu + 32768;           // 8388608 elements

    fused_pool_gather_kernel<<<1024, 256>>>(mu, sigma, out_mu, out_sig);
}

// round 9
// speedup vs baseline: 1.0084x; 1.0084x over previous
#include <cuda_runtime.h>

// Fused maxpool-argmax + sigma row-gather. (Resubmit of R6 design: prior bench
// died with cudaErrorSystemNotReady before any kernel ran — infra, not kernel.)
//
// Strategy: the scattered gather already touches every 32B sector of each
// selected row, so reading rows FULLY (coalesced float4 streaming) costs the
// same DRAM traffic. Stage 8 full rows in smem per phase, gather columns via
// LDS, write coalesced. Next phase's LDG.128s issue before the current
// gather (register double-buffer) so loads stay in flight across barriers.
//
// Grid: 128 bc * 8 chunks = 1024 blocks, 256 threads.
// Chunk owns output rows [32*chunk, 32*chunk+32); thread j owns column j.
__global__ __launch_bounds__(256, 4)
void fused_pool_gather_kernel(const float* __restrict__ mu,
                              const float* __restrict__ sigma,
                              float* __restrict__ out_mu,
                              float* __restrict__ out_sig) {
    __shared__ int   scol[256];
    __shared__ float srow[8 * 1024];      // 8 staged rows, 32 KB

    const int bc    = blockIdx.x >> 3;
    const int chunk = blockIdx.x & 7;
    const int j     = threadIdx.x;        // 0..255

    // ---- pool/argmax for window j (mu: 4KB/bc, L2-resident after first touch) ----
    const int ho = j >> 4;
    const int wo = j & 15;
    const float* base = mu + (size_t)bc * 1024;
    const int r0 = 2 * ho;
    const int c0 = 2 * wo;

    const float v0 = base[r0 * 32 + c0];
    const float v1 = base[r0 * 32 + c0 + 1];
    const float v2 = base[(r0 + 1) * 32 + c0];
    const float v3 = base[(r0 + 1) * 32 + c0 + 1];

    float m = v0; int k = 0;
    if (v1 > m) { m = v1; k = 1; }        // strict >: first-max, matches jnp.argmax
    if (v2 > m) { m = v2; k = 2; }
    if (v3 > m) { m = v3; k = 3; }

    const int cj = (r0 + (k >> 1)) * 32 + (c0 + (k & 1));
    scol[j] = cj;
    if (chunk == 0) out_mu[bc * 256 + j] = m;
    __syncthreads();

    // ---- staged row gather ----
    const float4* s4    = (const float4*)sigma + ((size_t)bc << 18);  // bc*1024*256 float4
    float*        obase = out_sig + (size_t)bc * 65536;
    const int     i0    = chunk * 32;

    // Prefetch stage 0: 8 full rows, thread j takes float4 column j of each.
    float4 v[8];
    #pragma unroll
    for (int u = 0; u < 8; ++u)
        v[u] = __ldcs(&s4[(size_t)scol[i0 + u] * 256 + j]);

    #pragma unroll
    for (int s = 0; s < 4; ++s) {
        // Commit current stage to smem.
        #pragma unroll
        for (int u = 0; u < 8; ++u) {
            float4* dst = (float4*)&srow[u * 1024] + j;
            *dst = v[u];
        }
        // Issue next stage's loads NOW — in flight during barrier + gather.
        if (s < 3) {
            #pragma unroll
            for (int u = 0; u < 8; ++u)
                v[u] = __ldcs(&s4[(size_t)scol[i0 + (s + 1) * 8 + u] * 256 + j]);
        }
        __syncthreads();

        // Gather: out[i][j] = row_i[cj]. Bank = image-col of pick; <=2-way conflicts.
        #pragma unroll
        for (int u = 0; u < 8; ++u)
            obase[(size_t)(i0 + s * 8 + u) * 256 + j] = srow[u * 1024 + cj];
        __syncthreads();                  // buffer safe to overwrite next stage
    }
}

extern "C" void kernel_launch(void* const* d_in, const int* in_sizes, int n_in,
                              void* d_out, int out_size) {
    const float* mu    = (const float*)d_in[0];
    const float* sigma = (const float*)d_in[1];
    if (n_in >= 2 && in_sizes[0] > in_sizes[1]) {
        sigma = (const float*)d_in[0];
        mu    = (const float*)d_in[1];
    }

    float* out_mu  = (float*)d_out;            // 32768 elements
    float* out_sig = out_mu + 32768;           // 8388608 elements

    fused_pool_gather_kernel<<<1024, 256>>>(mu, sigma, out_mu, out_sig);
}

// round 10
// speedup vs baseline: 1.0505x; 1.0418x over previous
#include <cuda_runtime.h>

// Fused maxpool-argmax + sigma row-gather, warp-autonomous version.
//
// Lesson from R6/R9: block-wide barriers created load-issue dead zones and
// killed occupancy. Here each warp independently streams one full 4KB sigma
// row (8x LDG.128, contiguous) into its PRIVATE smem slice, gathers 256
// picked columns via LDS, and writes coalesced. Only __syncwarp() — warps
// never wait on each other, so loads stay in flight continuously.
//
// Grid: 128 bc * 16 chunks = 2048 blocks, 256 threads (8 warps).
// Warp w of chunk handles output rows i0+2w and i0+2w+1.
__global__ __launch_bounds__(256, 5)
void fused_pool_gather_kernel(const float* __restrict__ mu,
                              const float* __restrict__ sigma,
                              float* __restrict__ out_mu,
                              float* __restrict__ out_sig) {
    __shared__ int   scol[256];
    __shared__ float srow[8][1024];       // one 4KB row slice per warp (32KB)

    const int bc    = blockIdx.x >> 4;    // 0..127
    const int chunk = blockIdx.x & 15;    // 0..15 (16 output rows each)
    const int tid   = threadIdx.x;

    // ---- pool/argmax for window `tid` (mu: 4KB/bc, L2-resident) ----
    {
        const int ho = tid >> 4;
        const int wo = tid & 15;
        const float* base = mu + (size_t)bc * 1024;
        const int r0 = 2 * ho;
        const int c0 = 2 * wo;

        const float v0 = base[r0 * 32 + c0];
        const float v1 = base[r0 * 32 + c0 + 1];
        const float v2 = base[(r0 + 1) * 32 + c0];
        const float v3 = base[(r0 + 1) * 32 + c0 + 1];

        float m = v0; int k = 0;
        if (v1 > m) { m = v1; k = 1; }    // strict >: first-max (jnp.argmax)
        if (v2 > m) { m = v2; k = 2; }
        if (v3 > m) { m = v3; k = 3; }

        scol[tid] = (r0 + (k >> 1)) * 32 + (c0 + (k & 1));
        if (chunk == 0) out_mu[bc * 256 + tid] = m;
    }
    __syncthreads();                       // the only block barrier

    const int w    = tid >> 5;             // warp id 0..7
    const int lane = tid & 31;

    const float4* s4    = (const float4*)sigma + ((size_t)bc << 18);
    float*        obase = out_sig + (size_t)bc * 65536;
    float4*       sw4   = (float4*)srow[w];
    const float*  swf   = srow[w];

    const int iA = chunk * 16 + 2 * w;     // this warp's two output rows
    const int iB = iA + 1;
    const int rA = scol[iA];
    const int rB = scol[iB];

    // ---- row A: stream full 4KB row (8x LDG.128, contiguous) ----
    float4 v[8];
    #pragma unroll
    for (int u = 0; u < 8; ++u)
        v[u] = __ldcs(&s4[(size_t)rA * 256 + u * 32 + lane]);

    #pragma unroll
    for (int u = 0; u < 8; ++u)            // STS row A into private slice
        sw4[u * 32 + lane] = v[u];

    // Issue row B's loads NOW — in flight during gather of A.
    #pragma unroll
    for (int u = 0; u < 8; ++u)
        v[u] = __ldcs(&s4[(size_t)rB * 256 + u * 32 + lane]);

    __syncwarp();

    // ---- gather A: out[iA][col] = rowA[scol[col]], coalesced STG.32 ----
    #pragma unroll
    for (int u = 0; u < 8; ++u) {
        const int col = u * 32 + lane;
        obase[(size_t)iA * 256 + col] = swf[scol[col]];
    }

    __syncwarp();                          // gather A done before overwrite
    #pragma unroll
    for (int u = 0; u < 8; ++u)            // STS row B
        sw4[u * 32 + lane] = v[u];
    __syncwarp();

    // ---- gather B ----
    #pragma unroll
    for (int u = 0; u < 8; ++u) {
        const int col = u * 32 + lane;
        obase[(size_t)iB * 256 + col] = swf[scol[col]];
    }
}

extern "C" void kernel_launch(void* const* d_in, const int* in_sizes, int n_in,
                              void* d_out, int out_size) {
    const float* mu    = (const float*)d_in[0];
    const float* sigma = (const float*)d_in[1];
    if (n_in >= 2 && in_sizes[0] > in_sizes[1]) {
        sigma = (const float*)d_in[0];
        mu    = (const float*)d_in[1];
    }

    float* out_mu  = (float*)d_out;            // 32768 elements
    float* out_sig = out_mu + 32768;           // 8388608 elements

    fused_pool_gather_kernel<<<2048, 256>>>(mu, sigma, out_mu, out_sig);
}